// round 16
// baseline (speedup 1.0000x reference)
#include <cuda_runtime.h>

// Langevin_2439541424651 — FINAL CHAMPION (converged R15 config).
// 131072 independent 200-step scalar recurrences; HBM-bound at the practical
// mixed-traffic ceiling: ~100MB noise read + ~301MB output write @ 5.4TB/s.
//
// Config rationale (all single-variable tested):
//  - scalar threads (131072 = full problem parallelism; float2/4 regress or tie)
//  - 1024 blocks x 128 threads: 6.92 CTAs/SM, near-perfect wave balance (R11 win)
//  - plain cached loads AND stores: any .cs hint halves achieved DRAM BW on
//    GB300 for this traffic (R3/R4/R13 — the single biggest effect found)
//  - unroll 16: ties best; longer scheduling window, regs stay at 32
//  - steps tensor folded into a coalesced prologue (no serialized tail kernel)
//  - algebra folded: t_old - t_new computed without rematerializing t_new

#define N_PART 1024
#define DX     128
#define STEPS  200
#define ND     (N_PART * DX)                      // 131072 threads
#define TOT_XT ((long)N_PART * STEPS * DX)

__global__ void __launch_bounds__(128) langevin_kernel(
    const float* __restrict__ x0,      // [N, DX]
    const float* __restrict__ y0,      // [N, DX]
    const float* __restrict__ mean,    // [DX]
    const float* __restrict__ var,     // [DX]
    const float* __restrict__ gammas,  // [STEPS]
    const float* __restrict__ noise,   // [STEPS, N, DX]
    float* __restrict__ x_tot,         // [N, STEPS, DX]
    float* __restrict__ y_tot,
    float* __restrict__ out,
    float* __restrict__ steps_out)     // [N, STEPS]
{
    __shared__ float s_g[STEPS];
    __shared__ float s_s[STEPS];

    for (int k = threadIdx.x; k < STEPS; k += blockDim.x) {
        float g = gammas[k];
        s_g[k] = g;
        s_s[k] = sqrtf(2.0f * g);
    }

    int tid = blockIdx.x * blockDim.x + threadIdx.x;   // 0 .. ND-1

    // Steps tensor [N, STEPS, 1]: coalesced prologue, no tail kernel.
    for (int i = tid; i < N_PART * STEPS; i += ND)
        steps_out[i] = (float)(i % STEPS);

    __syncthreads();

    int d = tid & (DX - 1);
    int n = tid >> 7;

    float x  = x0[tid];
    float yv = y0[tid];
    float m  = mean[d];
    float iv = 1.0f / var[d];

    long base = (long)n * STEPS * DX + d;
    const float* __restrict__ zp = noise + tid;

    // t_old = x - c*(x-m);  x_new = t_old + s*z
    // t_old - t_new = (t_old - x_new) + c*(x_new - m),  c = gamma/var
#pragma unroll 16
    for (int k = 0; k < STEPS; ++k) {
        float g = s_g[k];
        float s = s_s[k];
        float z = zp[(long)k * ND];

        float c     = g * iv;
        float t_old = fmaf(-c, x - m, x);
        float xn    = fmaf(s, z, t_old);
        float diff  = fmaf(c, xn - m, t_old - xn);
        x = xn;

        long o = base + (long)k * DX;
        x_tot[o] = xn;
        y_tot[o] = yv;
        out[o]   = diff;
    }
}

extern "C" void kernel_launch(void* const* d_in, const int* in_sizes, int n_in,
                              void* d_out, int out_size)
{
    const float* x0     = (const float*)d_in[0];
    const float* y0     = (const float*)d_in[1];
    const float* mean   = (const float*)d_in[2];
    const float* var    = (const float*)d_in[3];
    const float* gammas = (const float*)d_in[4];
    const float* noise  = (const float*)d_in[5];

    float* base  = (float*)d_out;
    float* x_tot = base;                 // [N, S, D]
    float* y_tot = base + TOT_XT;
    float* outp  = base + 2 * TOT_XT;
    float* steps = base + 3 * TOT_XT;    // [N, S, 1]

    langevin_kernel<<<ND / 128, 128>>>(x0, y0, mean, var, gammas, noise,
                                       x_tot, y_tot, outp, steps);
}